// round 5
// baseline (speedup 1.0000x reference)
#include <cuda_runtime.h>
#include <cstdint>

// SpatialEncoding: dense 8192x8192 scatter, last-write-wins over 8M edges.
//
// R5: P1 (proven) unchanged: smem-staged coarse binning, 2048 buckets x 4 rows.
// P2 split into half-buckets (2 rows, 64KB smem, 512 thr) so 3 CTAs/SM overlap
// the atomic-resolution phase with the DRAM store phase. Cursor reset moved to
// a tiny pre-kernel (idempotent; removes reset race between half-CTAs).
//
// Record (8B): hi = ((s&3)<<14) | d ; lo = ((e+1)<<3) | bias_idx
// Max lo per (row,col) == last write wins (keys unique, order-independent).

#define N_NODES    8192
#define BUCKETS    2048          // 4 src-rows per P1 bucket
#define STAGE_CAP  10            // lambda=4 per (bucket,CTA); overflow path below
#define CAP_G      5120          // per-bucket global slab (mean 3906, +19 sigma)
#define WAVE       8192          // edges per CTA in pass 1
#define P1_THREADS 1024
#define P2_THREADS 512

static __device__ unsigned long long g_bin[(size_t)BUCKETS * CAP_G];  // 80MB
static __device__ int                g_cur[BUCKETS * 8];              // 32B-padded

// ---------------- Pass 0: reset cursors (cheap, idempotent) ----------------
__global__ void reset_kernel() {
    g_cur[blockIdx.x * 1024 + threadIdx.x] = 0;
}

__device__ __forceinline__ void stage_edge(long e, int s, int d, int pl,
                                           unsigned long long* s_stage,
                                           int* s_cnt) {
    int idx = min(max(pl, 1), 5) - 1;                          // 0..4
    unsigned int key = (((unsigned int)e + 1u) << 3) | (unsigned int)idx;
    unsigned long long rec =
        ((unsigned long long)(unsigned int)(((s & 3) << 14) | d) << 32) |
        (unsigned long long)key;
    int bk  = s >> 2;
    int pos = atomicAdd(&s_cnt[bk], 1);
    if (pos < STAGE_CAP) {
        s_stage[bk * STAGE_CAP + pos] = rec;
    } else {
        int gp = atomicAdd(&g_cur[bk * 8], 1);                 // rare overflow
        if (gp < CAP_G)
            g_bin[(size_t)bk * CAP_G + gp] = rec;
    }
}

// ---------------- Pass 1: stage + packed flush ----------------
__global__ void __launch_bounds__(P1_THREADS)
bin_kernel(const int* __restrict__ src,
           const int* __restrict__ dst,
           const int* __restrict__ plen,
           long E) {
    extern __shared__ char smem[];
    unsigned long long* s_stage = (unsigned long long*)smem;           // 2048*10*8 = 160KB
    int* s_cnt = (int*)(smem + (size_t)BUCKETS * STAGE_CAP * 8);       // 8KB

    const int t = threadIdx.x;
    #pragma unroll
    for (int i = 0; i < BUCKETS / P1_THREADS; i++)
        s_cnt[t + i * P1_THREADS] = 0;
    __syncthreads();

    const long base = (long)blockIdx.x * WAVE;
    #pragma unroll
    for (int c = 0; c < WAVE / (P1_THREADS * 4); c++) {
        long e0 = base + (long)c * (P1_THREADS * 4) + (long)t * 4;
        if (e0 + 3 < E) {
            int4 s4 = *reinterpret_cast<const int4*>(&src[e0]);
            int4 d4 = *reinterpret_cast<const int4*>(&dst[e0]);
            int4 p4 = *reinterpret_cast<const int4*>(&plen[e0]);
            stage_edge(e0 + 0, s4.x, d4.x, p4.x, s_stage, s_cnt);
            stage_edge(e0 + 1, s4.y, d4.y, p4.y, s_stage, s_cnt);
            stage_edge(e0 + 2, s4.z, d4.z, p4.z, s_stage, s_cnt);
            stage_edge(e0 + 3, s4.w, d4.w, p4.w, s_stage, s_cnt);
        } else {
            for (long e = e0; e < E && e < e0 + 4; e++)
                stage_edge(e, src[e], dst[e], plen[e], s_stage, s_cnt);
        }
    }
    __syncthreads();

    // packed flush: each thread owns BUCKETS/P1_THREADS buckets
    #pragma unroll
    for (int i = 0; i < BUCKETS / P1_THREADS; i++) {
        int bk = t + i * P1_THREADS;
        int k = min(s_cnt[bk], STAGE_CAP);
        if (k > 0) {
            int gp = atomicAdd(&g_cur[bk * 8], k);
            unsigned long long* dp = &g_bin[(size_t)bk * CAP_G + gp];
            const unsigned long long* sp = &s_stage[bk * STAGE_CAP];
            #pragma unroll 4
            for (int j = 0; j < k; j++) {
                if (gp + j < CAP_G) dp[j] = sp[j];
            }
        }
    }
}

// ---------------- Pass 2: per-half-bucket resolve + convert ----------------
// grid = BUCKETS*2; blockIdx = (bucket<<1)|half so sibling CTAs are adjacent
// (second record read hits L2). Each CTA owns 2 rows = 64KB smem -> 3 CTAs/SM.
__global__ void __launch_bounds__(P2_THREADS, 3)
resolve_kernel(const float* __restrict__ b,
               float* __restrict__ out) {
    extern __shared__ char smem[];
    unsigned int* s_key = (unsigned int*)smem;          // 2*8192*4 = 64KB
    __shared__ float s_b[8];

    const int bk   = blockIdx.x >> 1;
    const unsigned int half = blockIdx.x & 1;
    const int t    = threadIdx.x;

    // zero 64KB of keys (uint4)
    uint4* kz = (uint4*)s_key;
    #pragma unroll
    for (int i = 0; i < (2 * N_NODES / 4) / P2_THREADS; i++)
        kz[t + i * P2_THREADS] = make_uint4(0u, 0u, 0u, 0u);
    if (t < 8) s_b[t] = (t < 5) ? b[t] : 0.0f;

    int cnt = g_cur[bk * 8];
    if (cnt > CAP_G) cnt = CAP_G;
    __syncthreads();

    // stream records; keep those whose srow is in our half; smem atomicMax
    const unsigned long long* __restrict__ recs = &g_bin[(size_t)bk * CAP_G];
    for (int i = t; i < cnt; i += P2_THREADS) {
        unsigned long long r = recs[i];
        unsigned int hi  = (unsigned int)(r >> 32);
        unsigned int key = (unsigned int)r;
        unsigned int srow = (hi >> 14) & 3u;
        if ((srow >> 1) == half) {
            unsigned int d = hi & 0x1FFFu;
            atomicMax(&s_key[((srow & 1u) << 13) | d], key);
        }
    }
    __syncthreads();

    // convert + contiguous 64KB output write (rows bk*4 + half*2 .. +1)
    float* __restrict__ ob = out + ((size_t)bk * 4 + half * 2) * N_NODES;
    #pragma unroll
    for (int i = 0; i < (2 * N_NODES / 4) / P2_THREADS; i++) {
        int j4 = t + i * P2_THREADS;
        uint4 k = kz[j4];
        float4 o;
        o.x = k.x ? s_b[k.x & 7u] : 0.0f;
        o.y = k.y ? s_b[k.y & 7u] : 0.0f;
        o.z = k.z ? s_b[k.z & 7u] : 0.0f;
        o.w = k.w ? s_b[k.w & 7u] : 0.0f;
        *reinterpret_cast<float4*>(&ob[j4 * 4]) = o;
    }
}

extern "C" void kernel_launch(void* const* d_in, const int* in_sizes, int n_in,
                              void* d_out, int out_size) {
    // metadata order: x [N,128] f32, src [E] i32, dst [E] i32,
    //                 path_len [E] i32, b [5] f32
    const int*   src  = (const int*)d_in[1];
    const int*   dst  = (const int*)d_in[2];
    const int*   plen = (const int*)d_in[3];
    const float* b    = (const float*)d_in[4];
    float*       out  = (float*)d_out;

    const long E = (long)in_sizes[1];   // 8,000,000

    const size_t p1_smem = (size_t)BUCKETS * STAGE_CAP * 8 + BUCKETS * 4;  // 168KB
    const size_t p2_smem = (size_t)2 * N_NODES * 4;                        // 64KB

    static bool attr_set = false;
    if (!attr_set) {
        cudaFuncSetAttribute(bin_kernel,
                             cudaFuncAttributeMaxDynamicSharedMemorySize, (int)p1_smem);
        cudaFuncSetAttribute(resolve_kernel,
                             cudaFuncAttributeMaxDynamicSharedMemorySize, (int)p2_smem);
        attr_set = true;
    }

    reset_kernel<<<BUCKETS * 8 / 1024, 1024>>>();
    {
        const int blocks = (int)((E + WAVE - 1) / WAVE);   // 977
        bin_kernel<<<blocks, P1_THREADS, p1_smem>>>(src, dst, plen, E);
    }
    {
        resolve_kernel<<<BUCKETS * 2, P2_THREADS, p2_smem>>>(b, out);
    }
}

// round 7
// speedup vs baseline: 1.1298x; 1.1298x over previous
#include <cuda_runtime.h>
#include <cstdint>

// SpatialEncoding: dense 8192x8192 scatter, last-write-wins over 8M edges.
//
// R6 (resubmit after infra failure): fine-grained binning, 4096 buckets x 2 rows.
//  P1: smem-staged binning (STAGE_CAP 6, ~208KB smem), packed flush.
//  P2: 1 CTA per bucket, 64KB smem (2 rows of keys) -> 3 CTAs/SM so the
//      atomic-resolution phase overlaps sibling CTAs' output stores.
//      Records loaded as uint4 (2 per LDG). CTA resets its own cursor.
//
// Record (8B): hi = ((s&1)<<13) | d ; lo = ((e+1)<<3) | bias_idx
// Max lo per (row,col) == last write wins (keys unique, order-independent).

#define N_NODES    8192
#define BUCKETS    4096          // 2 src-rows per bucket
#define STAGE_CAP  6             // lambda=2 per (bucket,CTA); overflow path below
#define CAP_G      2944          // per-bucket slab (mean 1953, sigma 44 -> +22 sigma)
#define WAVE       8192          // edges per CTA in pass 1
#define P1_THREADS 1024
#define P2_THREADS 512

static __device__ unsigned long long g_bin[(size_t)BUCKETS * CAP_G];  // 96MB
static __device__ int                g_cur[BUCKETS * 8];              // 32B-padded, zero-init

__device__ __forceinline__ void stage_edge(long e, int s, int d, int pl,
                                           unsigned long long* s_stage,
                                           int* s_cnt) {
    int idx = min(max(pl, 1), 5) - 1;                          // 0..4
    unsigned int key = (((unsigned int)e + 1u) << 3) | (unsigned int)idx;
    unsigned long long rec =
        ((unsigned long long)(unsigned int)(((s & 1) << 13) | d) << 32) |
        (unsigned long long)key;
    int bk  = s >> 1;
    int pos = atomicAdd(&s_cnt[bk], 1);
    if (pos < STAGE_CAP) {
        s_stage[bk * STAGE_CAP + pos] = rec;
    } else {
        int gp = atomicAdd(&g_cur[bk * 8], 1);                 // rare overflow
        if (gp < CAP_G)
            g_bin[(size_t)bk * CAP_G + gp] = rec;
    }
}

// ---------------- Pass 1: stage + packed flush ----------------
__global__ void __launch_bounds__(P1_THREADS)
bin_kernel(const int* __restrict__ src,
           const int* __restrict__ dst,
           const int* __restrict__ plen,
           long E) {
    extern __shared__ char smem[];
    unsigned long long* s_stage = (unsigned long long*)smem;           // 4096*6*8 = 192KB
    int* s_cnt = (int*)(smem + (size_t)BUCKETS * STAGE_CAP * 8);       // 16KB

    const int t = threadIdx.x;
    #pragma unroll
    for (int i = 0; i < BUCKETS / P1_THREADS; i++)
        s_cnt[t + i * P1_THREADS] = 0;
    __syncthreads();

    const long base = (long)blockIdx.x * WAVE;
    #pragma unroll
    for (int c = 0; c < WAVE / (P1_THREADS * 4); c++) {
        long e0 = base + (long)c * (P1_THREADS * 4) + (long)t * 4;
        if (e0 + 3 < E) {
            int4 s4 = *reinterpret_cast<const int4*>(&src[e0]);
            int4 d4 = *reinterpret_cast<const int4*>(&dst[e0]);
            int4 p4 = *reinterpret_cast<const int4*>(&plen[e0]);
            stage_edge(e0 + 0, s4.x, d4.x, p4.x, s_stage, s_cnt);
            stage_edge(e0 + 1, s4.y, d4.y, p4.y, s_stage, s_cnt);
            stage_edge(e0 + 2, s4.z, d4.z, p4.z, s_stage, s_cnt);
            stage_edge(e0 + 3, s4.w, d4.w, p4.w, s_stage, s_cnt);
        } else {
            for (long e = e0; e < E && e < e0 + 4; e++)
                stage_edge(e, src[e], dst[e], plen[e], s_stage, s_cnt);
        }
    }
    __syncthreads();

    // packed flush: each thread owns BUCKETS/P1_THREADS buckets
    #pragma unroll
    for (int i = 0; i < BUCKETS / P1_THREADS; i++) {
        int bk = t + i * P1_THREADS;
        int k = min(s_cnt[bk], STAGE_CAP);
        if (k > 0) {
            int gp = atomicAdd(&g_cur[bk * 8], k);
            unsigned long long* dp = &g_bin[(size_t)bk * CAP_G + gp];
            const unsigned long long* sp = &s_stage[bk * STAGE_CAP];
            #pragma unroll
            for (int j = 0; j < STAGE_CAP; j++) {
                if (j < k && gp + j < CAP_G) dp[j] = sp[j];
            }
        }
    }
}

// ---------------- Pass 2: per-bucket resolve + convert ----------------
__global__ void __launch_bounds__(P2_THREADS, 3)
resolve_kernel(const float* __restrict__ b,
               float* __restrict__ out) {
    extern __shared__ char smem[];
    unsigned int* s_key = (unsigned int*)smem;          // 2*8192*4 = 64KB
    __shared__ float s_b[8];

    const int bk = blockIdx.x;
    const int t  = threadIdx.x;

    // zero 64KB of keys (uint4)
    uint4* kz = (uint4*)s_key;
    #pragma unroll
    for (int i = 0; i < (2 * N_NODES / 4) / P2_THREADS; i++)
        kz[t + i * P2_THREADS] = make_uint4(0u, 0u, 0u, 0u);
    if (t < 8) s_b[t] = (t < 5) ? b[t] : 0.0f;

    int cnt = g_cur[bk * 8];
    if (cnt > CAP_G) cnt = CAP_G;
    __syncthreads();

    // stream records as uint4 (2 records per load); smem atomicMax resolves
    const unsigned long long* __restrict__ recs = &g_bin[(size_t)bk * CAP_G];
    const uint4* __restrict__ recs4 = reinterpret_cast<const uint4*>(recs);
    const int npair = cnt >> 1;
    for (int i = t; i < npair; i += P2_THREADS) {
        uint4 r = recs4[i];
        // record 0: lo=r.x key, hi=r.y addr ; record 1: lo=r.z, hi=r.w
        atomicMax(&s_key[r.y & 0x3FFFu], r.x);
        atomicMax(&s_key[r.w & 0x3FFFu], r.z);
    }
    if (t == 0 && (cnt & 1)) {
        unsigned long long r = recs[cnt - 1];
        atomicMax(&s_key[(unsigned int)(r >> 32) & 0x3FFFu], (unsigned int)r);
    }
    __syncthreads();

    // convert + contiguous 64KB output write (rows bk*2, bk*2+1)
    float* __restrict__ ob = out + (size_t)bk * 2 * N_NODES;
    #pragma unroll
    for (int i = 0; i < (2 * N_NODES / 4) / P2_THREADS; i++) {
        int j4 = t + i * P2_THREADS;
        uint4 k = kz[j4];
        float4 o;
        o.x = k.x ? s_b[k.x & 7u] : 0.0f;
        o.y = k.y ? s_b[k.y & 7u] : 0.0f;
        o.z = k.z ? s_b[k.z & 7u] : 0.0f;
        o.w = k.w ? s_b[k.w & 7u] : 0.0f;
        *reinterpret_cast<float4*>(&ob[j4 * 4]) = o;
    }

    // reset our cursor for the next graph replay (deterministic counts)
    if (t == 0) g_cur[bk * 8] = 0;
}

extern "C" void kernel_launch(void* const* d_in, const int* in_sizes, int n_in,
                              void* d_out, int out_size) {
    // metadata order: x [N,128] f32, src [E] i32, dst [E] i32,
    //                 path_len [E] i32, b [5] f32
    const int*   src  = (const int*)d_in[1];
    const int*   dst  = (const int*)d_in[2];
    const int*   plen = (const int*)d_in[3];
    const float* b    = (const float*)d_in[4];
    float*       out  = (float*)d_out;

    const long E = (long)in_sizes[1];   // 8,000,000

    const size_t p1_smem = (size_t)BUCKETS * STAGE_CAP * 8 + BUCKETS * 4;  // 208KB
    const size_t p2_smem = (size_t)2 * N_NODES * 4;                        // 64KB

    static bool attr_set = false;
    if (!attr_set) {
        cudaFuncSetAttribute(bin_kernel,
                             cudaFuncAttributeMaxDynamicSharedMemorySize, (int)p1_smem);
        cudaFuncSetAttribute(resolve_kernel,
                             cudaFuncAttributeMaxDynamicSharedMemorySize, (int)p2_smem);
        attr_set = true;
    }

    {
        const int blocks = (int)((E + WAVE - 1) / WAVE);   // 977
        bin_kernel<<<blocks, P1_THREADS, p1_smem>>>(src, dst, plen, E);
    }
    {
        resolve_kernel<<<BUCKETS, P2_THREADS, p2_smem>>>(b, out);
    }
}